// round 1
// baseline (speedup 1.0000x reference)
#include <cuda_runtime.h>
#include <math.h>

// Problem constants (fixed by setup_inputs)
#define BB   4
#define CC   64
#define OO   64
#define HH   128
#define WW   128
#define HWSZ (HH * WW)

// Scratch for offset-conv output: [B][27][H][W]
__device__ float g_om[BB * 27 * HWSZ];

// ---------------------------------------------------------------------------
// Kernel 1: 3x3 conv producing 27 offset/mask channels.
// One CTA per (b, y) row. smem: w_s[576][32] (o padded 27->32), feat_s[64][3][132].
// Thread tile: 4 o x 4 px.  256 threads.
// ---------------------------------------------------------------------------
#define K1_SMEM_W   (576 * 32)
#define K1_SMEM_F   (CC * 3 * 132)
#define K1_SMEM_BYTES ((K1_SMEM_W + K1_SMEM_F) * 4)

__global__ __launch_bounds__(256, 1)
void offset_conv_kernel(const float* __restrict__ feat,
                        const float* __restrict__ w_off,
                        const float* __restrict__ b_off)
{
    extern __shared__ float smem[];
    float* w_s    = smem;                 // [k=576][o=32]
    float* feat_s = smem + K1_SMEM_W;     // [c][r=3][xx=132]

    const int y   = blockIdx.x;
    const int b   = blockIdx.y;
    const int tid = threadIdx.x;

    // load weights: w_s[k*32 + o] = w_off[o][c][r] with k = c*9 + r
    for (int idx = tid; idx < K1_SMEM_W; idx += 256) {
        int o = idx & 31;
        int k = idx >> 5;
        int c = k / 9;
        int r = k - c * 9;
        w_s[idx] = (o < 27) ? w_off[(o * CC + c) * 9 + r] : 0.f;
    }
    // load feat rows y-1..y+1 into [c][r][xx], xx=0 maps to x=-1, zero-padded
    const float* fb = feat + (size_t)b * CC * HWSZ;
    for (int idx = tid; idx < K1_SMEM_F; idx += 256) {
        int xx = idx % 132;
        int t  = idx / 132;
        int r  = t % 3;
        int c  = t / 3;
        int yy = y + r - 1;
        int xg = xx - 1;
        float v = 0.f;
        if (yy >= 0 && yy < HH && xg >= 0 && xg < WW)
            v = fb[(c * HH + yy) * WW + xg];
        feat_s[idx] = v;
    }
    __syncthreads();

    const int o0  = (tid & 7) * 4;   // 8 o-groups (0..28)
    const int px0 = (tid >> 3) * 4;  // 32 px-groups

    float acc[4][4];
#pragma unroll
    for (int j = 0; j < 4; j++)
#pragma unroll
        for (int i = 0; i < 4; i++) acc[j][i] = 0.f;

    for (int c = 0; c < CC; c++) {
#pragma unroll
        for (int ky = 0; ky < 3; ky++) {
            const float* row = &feat_s[(c * 3 + ky) * 132 + px0];
            float f[6];
#pragma unroll
            for (int i = 0; i < 6; i++) f[i] = row[i];
#pragma unroll
            for (int kx = 0; kx < 3; kx++) {
                const float4 w4 = *(const float4*)&w_s[((c * 9 + ky * 3 + kx) << 5) + o0];
                float wv[4] = {w4.x, w4.y, w4.z, w4.w};
#pragma unroll
                for (int j = 0; j < 4; j++)
#pragma unroll
                    for (int i = 0; i < 4; i++)
                        acc[j][i] = fmaf(wv[j], f[i + kx], acc[j][i]);
            }
        }
    }

#pragma unroll
    for (int j = 0; j < 4; j++) {
        int o = o0 + j;
        if (o < 27) {
            float bo = b_off[o];
            float* op = &g_om[((b * 27 + o) * HH + y) * WW + px0];
            float4 v = make_float4(acc[j][0] + bo, acc[j][1] + bo,
                                   acc[j][2] + bo, acc[j][3] + bo);
            *(float4*)op = v;
        }
    }
}

// ---------------------------------------------------------------------------
// Kernel 2: fused bilinear sampling + deform GEMM + bias + ReLU.
// One CTA per (b, y) row: out tile 64 o x 128 px, K = 576 (c,tap).
// smem: w_s[576][64], params (4 idx + 4 wgt per (tap,px)), vals[16][128].
// Thread tile: 4 o x 8 px.  256 threads.
// ---------------------------------------------------------------------------
#define K2_SMEM_W   (576 * 64)                 // 36864 floats
#define K2_NPAR     (9 * 128)                  // 1152
#define K2_OFF_WGT  (K2_SMEM_W)                // 4*1152 floats
#define K2_OFF_IDX  (K2_SMEM_W + 4 * K2_NPAR)  // 4*1152 ints
#define K2_OFF_VAL  (K2_SMEM_W + 8 * K2_NPAR)  // 16*128 floats
#define K2_SMEM_FLOATS (K2_SMEM_W + 8 * K2_NPAR + 16 * 128)
#define K2_SMEM_BYTES  (K2_SMEM_FLOATS * 4)

__global__ __launch_bounds__(256, 1)
void deform_gemm_kernel(const float* __restrict__ x,
                        const float* __restrict__ w_def,
                        const float* __restrict__ b_def,
                        float* __restrict__ out)
{
    extern __shared__ float smem[];
    float* w_s    = smem;                       // [k=576][o=64]
    float* wgt_s  = smem + K2_OFF_WGT;          // [corner=4][1152]
    int*   idx_s  = (int*)(smem + K2_OFF_IDX);  // [corner=4][1152]
    float* vals_s = smem + K2_OFF_VAL;          // [c_local=16][128]

    const int y   = blockIdx.x;
    const int b   = blockIdx.y;
    const int tid = threadIdx.x;

    // load w_def: w_s[k*64 + o] = w_def[o][c][r], k = c*9 + r
    for (int idx = tid; idx < K2_SMEM_W; idx += 256) {
        int o = idx & 63;
        int k = idx >> 6;
        int c = k / 9;
        int r = k - c * 9;
        w_s[idx] = w_def[(o * CC + c) * 9 + r];
    }

    // sampling params: one per (tap, px)
    for (int e = tid; e < K2_NPAR; e += 256) {
        int k  = e >> 7;
        int px = e & 127;
        int base = (b * 27 * HH + y) * WW + px;
        float offx = g_om[base + k * HWSZ];
        float offy = g_om[base + (9 + k) * HWSZ];
        float mz   = g_om[base + (18 + k) * HWSZ];
        float m    = 1.f / (1.f + __expf(-mz));    // sigmoid

        float ys = (float)(y + k / 3 - 1) + offy;
        float xs = (float)(px + (k % 3) - 1) + offx;
        float y0f = floorf(ys), x0f = floorf(xs);
        float wy1 = ys - y0f,   wx1 = xs - x0f;
        int iy0 = (int)y0f, ix0 = (int)x0f;

#pragma unroll
        for (int corner = 0; corner < 4; corner++) {
            int oy = corner >> 1, ox = corner & 1;
            int yy = iy0 + oy, xx = ix0 + ox;
            bool valid = (yy >= 0) && (yy < HH) && (xx >= 0) && (xx < WW);
            float wy = oy ? wy1 : (1.f - wy1);
            float wx = ox ? wx1 : (1.f - wx1);
            float wgt = valid ? (wy * wx * m) : 0.f;
            int yc = min(max(yy, 0), HH - 1);
            int xc = min(max(xx, 0), WW - 1);
            wgt_s[corner * K2_NPAR + e] = wgt;
            idx_s[corner * K2_NPAR + e] = yc * WW + xc;
        }
    }
    __syncthreads();

    // GEMM thread tiling: 4 o x 8 px
    const int o0  = (tid & 15) * 4;
    const int px0 = (tid >> 4) * 8;
    // sample-fill tiling: each thread owns one px, 8 channels per chunk
    const int spx = tid & 127;
    const int cb  = (tid >> 7) * 8;

    const float* xb = x + (size_t)b * CC * HWSZ;

    float acc[4][8];
#pragma unroll
    for (int j = 0; j < 4; j++)
#pragma unroll
        for (int i = 0; i < 8; i++) acc[j][i] = 0.f;

    for (int tap = 0; tap < 9; tap++) {
        const int e = tap * 128 + spx;
        const float w0 = wgt_s[e];
        const float w1 = wgt_s[K2_NPAR + e];
        const float w2 = wgt_s[2 * K2_NPAR + e];
        const float w3 = wgt_s[3 * K2_NPAR + e];
        const int   i0 = idx_s[e];
        const int   i1 = idx_s[K2_NPAR + e];
        const int   i2 = idx_s[2 * K2_NPAR + e];
        const int   i3 = idx_s[3 * K2_NPAR + e];

        for (int cc = 0; cc < CC; cc += 16) {
            __syncthreads();   // protect vals_s from previous GEMM readers
            // fill vals_s[16][128]
#pragma unroll
            for (int r = 0; r < 8; r++) {
                int c = cc + cb + r;
                const float* xc = xb + c * HWSZ;
                float v = w0 * xc[i0] + w1 * xc[i1] + w2 * xc[i2] + w3 * xc[i3];
                vals_s[(cb + r) * 128 + spx] = v;
            }
            __syncthreads();
            // register-tile GEMM over this 16-channel chunk
#pragma unroll
            for (int cl = 0; cl < 16; cl++) {
                const float4 w4 = *(const float4*)&w_s[((cc + cl) * 9 + tap) * 64 + o0];
                const float4 va = *(const float4*)&vals_s[cl * 128 + px0];
                const float4 vb = *(const float4*)&vals_s[cl * 128 + px0 + 4];
                float wv[4] = {w4.x, w4.y, w4.z, w4.w};
                float vv[8] = {va.x, va.y, va.z, va.w, vb.x, vb.y, vb.z, vb.w};
#pragma unroll
                for (int j = 0; j < 4; j++)
#pragma unroll
                    for (int i = 0; i < 8; i++)
                        acc[j][i] = fmaf(wv[j], vv[i], acc[j][i]);
            }
        }
    }

    // epilogue: bias + relu
#pragma unroll
    for (int j = 0; j < 4; j++) {
        int o = o0 + j;
        float bo = b_def[o];
        float* op = out + ((size_t)(b * OO + o) * HH + y) * WW + px0;
        float4 r0, r1;
        r0.x = fmaxf(acc[j][0] + bo, 0.f);
        r0.y = fmaxf(acc[j][1] + bo, 0.f);
        r0.z = fmaxf(acc[j][2] + bo, 0.f);
        r0.w = fmaxf(acc[j][3] + bo, 0.f);
        r1.x = fmaxf(acc[j][4] + bo, 0.f);
        r1.y = fmaxf(acc[j][5] + bo, 0.f);
        r1.z = fmaxf(acc[j][6] + bo, 0.f);
        r1.w = fmaxf(acc[j][7] + bo, 0.f);
        *(float4*)op       = r0;
        *(float4*)(op + 4) = r1;
    }
}

// ---------------------------------------------------------------------------
extern "C" void kernel_launch(void* const* d_in, const int* in_sizes, int n_in,
                              void* d_out, int out_size)
{
    const float* x     = (const float*)d_in[0];
    const float* feat  = (const float*)d_in[1];
    const float* w_off = (const float*)d_in[2];
    const float* b_off = (const float*)d_in[3];
    const float* w_def = (const float*)d_in[4];
    const float* b_def = (const float*)d_in[5];
    float* out = (float*)d_out;

    cudaFuncSetAttribute(offset_conv_kernel,
                         cudaFuncAttributeMaxDynamicSharedMemorySize, K1_SMEM_BYTES);
    cudaFuncSetAttribute(deform_gemm_kernel,
                         cudaFuncAttributeMaxDynamicSharedMemorySize, K2_SMEM_BYTES);

    dim3 grid(HH, BB);
    offset_conv_kernel<<<grid, 256, K1_SMEM_BYTES>>>(feat, w_off, b_off);
    deform_gemm_kernel<<<grid, 256, K2_SMEM_BYTES>>>(x, w_def, b_def, out);
}

// round 2
// speedup vs baseline: 2.1150x; 2.1150x over previous
#include <cuda_runtime.h>
#include <math.h>

// Problem constants (fixed by setup_inputs)
#define BB   4
#define CC   64
#define OO   64
#define HH   128
#define WW   128
#define HWSZ (HH * WW)

// Scratch for offset-conv output: [B][27][H][W]
__device__ float g_om[BB * 27 * HWSZ];

// ---------------------------------------------------------------------------
// Kernel 1: 3x3 conv producing 27 offset/mask channels (padded to 32 in smem).
// One CTA per (b, 2 rows). 512 threads. Thread tile 4o x 4px.
// smem: w_s[576][32], feat_s[64][4][136] (rows y0-1..y0+2, x halo, pad 136).
// o-group = tid>>6 -> warp-uniform -> weight LDS is broadcast.
// ---------------------------------------------------------------------------
#define K1_W_FLOATS (576 * 32)
#define K1_F_FLOATS (CC * 4 * 136)
#define K1_SMEM_BYTES ((K1_W_FLOATS + K1_F_FLOATS) * 4)

__global__ __launch_bounds__(512, 1)
void offset_conv_kernel(const float* __restrict__ feat,
                        const float* __restrict__ w_off,
                        const float* __restrict__ b_off)
{
    extern __shared__ float smem[];
    float* w_s    = smem;                 // [k=576][o=32]
    float* feat_s = smem + K1_W_FLOATS;   // [c][rr=4][136]

    const int y0  = blockIdx.x * 2;
    const int b   = blockIdx.y;
    const int tid = threadIdx.x;

    // weights: w_s[k*32 + o] = w_off[o][c][r], k = c*9 + r  (o>=27 -> 0)
    for (int idx = tid; idx < K1_W_FLOATS; idx += 512) {
        int o = idx & 31;
        int k = idx >> 5;
        int c = k / 9;
        int r = k - c * 9;
        w_s[idx] = (o < 27) ? w_off[(o * CC + c) * 9 + r] : 0.f;
    }
    // feat rows y0-1 .. y0+2, x halo (-1..130), padded width 136
    const float* fb = feat + (size_t)b * CC * HWSZ;
    for (int idx = tid; idx < K1_F_FLOATS; idx += 512) {
        int xx = idx % 136;      // 0 maps to x=-1
        int t  = idx / 136;
        int rr = t & 3;
        int c  = t >> 2;
        int yy = y0 - 1 + rr;
        int xg = xx - 1;
        float v = 0.f;
        if (xx < 132 && yy >= 0 && yy < HH && xg >= 0 && xg < WW)
            v = fb[(c * HH + yy) * WW + xg];
        feat_s[idx] = v;
    }
    __syncthreads();

    const int o0   = (tid >> 6) * 4;        // warp-uniform
    const int px0  = (tid & 63) * 4;        // 0..252
    const int rowo = px0 >> 7;              // 0 or 1
    const int xloc = px0 & 127;             // multiple of 4

    float acc[4][4];
#pragma unroll
    for (int j = 0; j < 4; j++)
#pragma unroll
        for (int i = 0; i < 4; i++) acc[j][i] = 0.f;

    for (int c = 0; c < CC; c++) {
#pragma unroll
        for (int ky = 0; ky < 3; ky++) {
            const int rr = rowo + ky;
            const float* row = &feat_s[(c * 4 + rr) * 136 + xloc];
            float4 fa = *(const float4*)row;
            float4 fbv = *(const float4*)(row + 4);
            float f[8] = {fa.x, fa.y, fa.z, fa.w, fbv.x, fbv.y, fbv.z, fbv.w};
#pragma unroll
            for (int kx = 0; kx < 3; kx++) {
                const float4 w4 = *(const float4*)&w_s[((c * 9 + ky * 3 + kx) << 5) + o0];
                float wv[4] = {w4.x, w4.y, w4.z, w4.w};
#pragma unroll
                for (int j = 0; j < 4; j++)
#pragma unroll
                    for (int i = 0; i < 4; i++)
                        acc[j][i] = fmaf(wv[j], f[i + kx], acc[j][i]);
            }
        }
    }

    const int yout = y0 + rowo;
#pragma unroll
    for (int j = 0; j < 4; j++) {
        int o = o0 + j;
        if (o < 27) {
            float bo = b_off[o];
            float* op = &g_om[((b * 27 + o) * HH + yout) * WW + xloc];
            *(float4*)op = make_float4(acc[j][0] + bo, acc[j][1] + bo,
                                       acc[j][2] + bo, acc[j][3] + bo);
        }
    }
}

// ---------------------------------------------------------------------------
// Kernel 2: fused bilinear sampling + deform GEMM + bias + ReLU.
// One CTA per (b, 2 rows): 64 o x 256 px tile, K = 576. 256 threads.
// Thread tile 8o x 8px (two 4-px segments: same x on both rows).
// o-group = tid>>5 -> warp-uniform weight broadcast LDS.
// smem: w_s[576][64] (147KB) + params (wy,wx,m,packed y0x0 per tap,px)
//       + vals[32][256] sample chunk.
// ---------------------------------------------------------------------------
#define K2_W     (576 * 64)     // 36864
#define K2_NP    (9 * 256)      // 2304
#define K2_OFF_PY (K2_W)
#define K2_OFF_PX (K2_W + K2_NP)
#define K2_OFF_PM (K2_W + 2 * K2_NP)
#define K2_OFF_PI (K2_W + 3 * K2_NP)
#define K2_OFF_V  (K2_W + 4 * K2_NP)
#define K2_FLOATS (K2_W + 4 * K2_NP + 32 * 256)
#define K2_SMEM_BYTES (K2_FLOATS * 4)

__global__ __launch_bounds__(256, 1)
void deform_gemm_kernel(const float* __restrict__ x,
                        const float* __restrict__ w_def,
                        const float* __restrict__ b_def,
                        float* __restrict__ out)
{
    extern __shared__ float smem[];
    float* w_s   = smem;                        // [k=576][o=64]
    float* parY  = smem + K2_OFF_PY;            // wy1 per (tap,px)
    float* parX  = smem + K2_OFF_PX;            // wx1
    float* parM  = smem + K2_OFF_PM;            // sigmoid(mask)
    int*   parI  = (int*)(smem + K2_OFF_PI);    // packed (y0+256,x0+256)
    float* vals  = smem + K2_OFF_V;             // [c_local=32][px=256]

    const int y0  = blockIdx.x * 2;
    const int b   = blockIdx.y;
    const int tid = threadIdx.x;

    // load w_def: w_s[k*64 + o], k = c*9 + r
    for (int idx = tid; idx < K2_W; idx += 256) {
        int o = idx & 63;
        int k = idx >> 6;
        int c = k / 9;
        int r = k - c * 9;
        w_s[idx] = w_def[(o * CC + c) * 9 + r];
    }

    // sampling params: one entry per (tap, px); px = tid
    {
        const int px   = tid;
        const int yrow = y0 + (px >> 7);
        const int gx   = px & 127;
        const int base = (b * 27 * HH + yrow) * WW + gx;
#pragma unroll
        for (int tap = 0; tap < 9; tap++) {
            int e = tap * 256 + px;
            float offx = g_om[base + tap * HWSZ];
            float offy = g_om[base + (9 + tap) * HWSZ];
            float mz   = g_om[base + (18 + tap) * HWSZ];
            float m    = 1.f / (1.f + __expf(-mz));
            float ys = (float)(yrow + tap / 3 - 1) + offy;
            float xs = (float)(gx + tap % 3 - 1) + offx;
            float y0f = floorf(ys), x0f = floorf(xs);
            parY[e] = ys - y0f;
            parX[e] = xs - x0f;
            parM[e] = m;
            parI[e] = (((int)y0f + 256) << 16) | ((int)x0f + 256);
        }
    }
    __syncthreads();

    const int pxa = (tid & 31) * 4;     // 0..124 (x on both rows)
    const int o0  = (tid >> 5) * 8;     // warp-uniform

    const float* xb = x + (size_t)b * CC * HWSZ;

    float acc[8][8];
#pragma unroll
    for (int j = 0; j < 8; j++)
#pragma unroll
        for (int i = 0; i < 8; i++) acc[j][i] = 0.f;

    for (int tap = 0; tap < 9; tap++) {
        // this thread's sampling params for the fill phase (its own px)
        const int e = tap * 256 + tid;
        const float wy1 = parY[e];
        const float wx1 = parX[e];
        const float m   = parM[e];
        const int   pi  = parI[e];
        const int iy0 = (pi >> 16) - 256;
        const int ix0 = (pi & 0xffff) - 256;

        float cw[4];
        int   ci[4];
#pragma unroll
        for (int corner = 0; corner < 4; corner++) {
            int oy = corner >> 1, ox = corner & 1;
            int yy = iy0 + oy, xx = ix0 + ox;
            bool valid = (yy >= 0) && (yy < HH) && (xx >= 0) && (xx < WW);
            float wy = oy ? wy1 : (1.f - wy1);
            float wx = ox ? wx1 : (1.f - wx1);
            cw[corner] = valid ? (wy * wx * m) : 0.f;
            int yc = min(max(yy, 0), HH - 1);
            int xc = min(max(xx, 0), WW - 1);
            ci[corner] = yc * WW + xc;
        }

        for (int cc = 0; cc < CC; cc += 32) {
            __syncthreads();          // protect vals from previous GEMM readers
            // fill vals[32][256]; this thread handles its px for 32 channels
#pragma unroll 8
            for (int r = 0; r < 32; r++) {
                const float* xc = xb + (cc + r) * HWSZ;
                float v = cw[0] * xc[ci[0]] + cw[1] * xc[ci[1]]
                        + cw[2] * xc[ci[2]] + cw[3] * xc[ci[3]];
                vals[r * 256 + tid] = v;
            }
            __syncthreads();
            // register-tile GEMM over this 32-channel chunk
#pragma unroll 8
            for (int cl = 0; cl < 32; cl++) {
                const int k = (cc + cl) * 9 + tap;
                const float4 wA = *(const float4*)&w_s[k * 64 + o0];
                const float4 wB = *(const float4*)&w_s[k * 64 + o0 + 4];
                const float4 vA = *(const float4*)&vals[cl * 256 + pxa];
                const float4 vB = *(const float4*)&vals[cl * 256 + pxa + 128];
                float wv[8] = {wA.x, wA.y, wA.z, wA.w, wB.x, wB.y, wB.z, wB.w};
                float vv[8] = {vA.x, vA.y, vA.z, vA.w, vB.x, vB.y, vB.z, vB.w};
#pragma unroll
                for (int j = 0; j < 8; j++)
#pragma unroll
                    for (int i = 0; i < 8; i++)
                        acc[j][i] = fmaf(wv[j], vv[i], acc[j][i]);
            }
        }
    }

    // epilogue: bias + relu; i 0..3 -> row y0 (x=pxa+i), i 4..7 -> row y0+1
#pragma unroll
    for (int j = 0; j < 8; j++) {
        int o = o0 + j;
        float bo = b_def[o];
        float* op0 = out + ((size_t)(b * OO + o) * HH + y0) * WW + pxa;
        float* op1 = op0 + WW;
        *(float4*)op0 = make_float4(fmaxf(acc[j][0] + bo, 0.f),
                                    fmaxf(acc[j][1] + bo, 0.f),
                                    fmaxf(acc[j][2] + bo, 0.f),
                                    fmaxf(acc[j][3] + bo, 0.f));
        *(float4*)op1 = make_float4(fmaxf(acc[j][4] + bo, 0.f),
                                    fmaxf(acc[j][5] + bo, 0.f),
                                    fmaxf(acc[j][6] + bo, 0.f),
                                    fmaxf(acc[j][7] + bo, 0.f));
    }
}

// ---------------------------------------------------------------------------
extern "C" void kernel_launch(void* const* d_in, const int* in_sizes, int n_in,
                              void* d_out, int out_size)
{
    const float* x     = (const float*)d_in[0];
    const float* feat  = (const float*)d_in[1];
    const float* w_off = (const float*)d_in[2];
    const float* b_off = (const float*)d_in[3];
    const float* w_def = (const float*)d_in[4];
    const float* b_def = (const float*)d_in[5];
    float* out = (float*)d_out;

    cudaFuncSetAttribute(offset_conv_kernel,
                         cudaFuncAttributeMaxDynamicSharedMemorySize, K1_SMEM_BYTES);
    cudaFuncSetAttribute(deform_gemm_kernel,
                         cudaFuncAttributeMaxDynamicSharedMemorySize, K2_SMEM_BYTES);

    dim3 grid(HH / 2, BB);
    offset_conv_kernel<<<grid, 512, K1_SMEM_BYTES>>>(feat, w_off, b_off);
    deform_gemm_kernel<<<grid, 256, K2_SMEM_BYTES>>>(x, w_def, b_def, out);
}

// round 3
// speedup vs baseline: 2.1741x; 1.0279x over previous
#include <cuda_runtime.h>
#include <math.h>

// Problem constants (fixed by setup_inputs)
#define BB   4
#define CC   64
#define OO   64
#define HH   128
#define WW   128
#define HWSZ (HH * WW)

// Scratch for offset-conv output: [B][27][H][W]
__device__ float g_om[BB * 27 * HWSZ];

typedef unsigned long long u64;

// ---- packed fp32x2 helpers (Blackwell FFMA2 path) ----
__device__ __forceinline__ u64 dup2(float v) {
    u64 r; asm("mov.b64 %0, {%1, %1};" : "=l"(r) : "f"(v)); return r;
}
__device__ __forceinline__ void fma2(u64& d, u64 a, u64 b) {
    asm("fma.rn.f32x2 %0, %1, %2, %0;" : "+l"(d) : "l"(a), "l"(b));
}
__device__ __forceinline__ void unpack2(u64 v, float& lo, float& hi) {
    asm("mov.b64 {%0, %1}, %2;" : "=f"(lo), "=f"(hi) : "l"(v));
}

// ---------------------------------------------------------------------------
// Kernel 1: 3x3 conv producing 27 offset/mask channels (padded to 32 in smem).
// One CTA per (b, 2 rows). 512 threads. Thread tile 4o x 4px, o-paired f32x2.
// smem: w_s[576][32], feat_s[64][4][136].
// ---------------------------------------------------------------------------
#define K1_W_FLOATS (576 * 32)
#define K1_F_FLOATS (CC * 4 * 136)
#define K1_SMEM_BYTES ((K1_W_FLOATS + K1_F_FLOATS) * 4)

__global__ __launch_bounds__(512, 1)
void offset_conv_kernel(const float* __restrict__ feat,
                        const float* __restrict__ w_off,
                        const float* __restrict__ b_off)
{
    extern __shared__ float smem[];
    float* w_s    = smem;                 // [k=576][o=32]
    float* feat_s = smem + K1_W_FLOATS;   // [c][rr=4][136]

    const int y0  = blockIdx.x * 2;
    const int b   = blockIdx.y;
    const int tid = threadIdx.x;

    // weights: w_s[k*32 + o] = w_off[o][c][r], k = c*9 + r  (o>=27 -> 0)
    for (int idx = tid; idx < K1_W_FLOATS; idx += 512) {
        int o = idx & 31;
        int k = idx >> 5;
        int c = k / 9;
        int r = k - c * 9;
        w_s[idx] = (o < 27) ? w_off[(o * CC + c) * 9 + r] : 0.f;
    }
    // feat rows y0-1 .. y0+2, x halo (-1..130), padded width 136
    const float* fb = feat + (size_t)b * CC * HWSZ;
    for (int idx = tid; idx < K1_F_FLOATS; idx += 512) {
        int xx = idx % 136;      // 0 maps to x=-1
        int t  = idx / 136;
        int rr = t & 3;
        int c  = t >> 2;
        int yy = y0 - 1 + rr;
        int xg = xx - 1;
        float v = 0.f;
        if (xx < 132 && yy >= 0 && yy < HH && xg >= 0 && xg < WW)
            v = fb[(c * HH + yy) * WW + xg];
        feat_s[idx] = v;
    }
    __syncthreads();

    const int o0   = (tid >> 6) * 4;        // warp-uniform
    const int px0  = (tid & 63) * 4;
    const int rowo = px0 >> 7;              // 0 or 1
    const int xloc = px0 & 127;

    u64 acc2[2][4];                         // o-pairs x 4 px
#pragma unroll
    for (int j = 0; j < 2; j++)
#pragma unroll
        for (int i = 0; i < 4; i++) acc2[j][i] = 0ULL;

    for (int c = 0; c < CC; c++) {
#pragma unroll
        for (int ky = 0; ky < 3; ky++) {
            const float* row = &feat_s[(c * 4 + rowo + ky) * 136 + xloc];
            float4 fa = *(const float4*)row;
            float2 fb2 = *(const float2*)(row + 4);
            float f[6] = {fa.x, fa.y, fa.z, fa.w, fb2.x, fb2.y};
            u64 fd[6];
#pragma unroll
            for (int t = 0; t < 6; t++) fd[t] = dup2(f[t]);
#pragma unroll
            for (int kx = 0; kx < 3; kx++) {
                const ulonglong2 wp =
                    *(const ulonglong2*)&w_s[((c * 9 + ky * 3 + kx) << 5) + o0];
#pragma unroll
                for (int i = 0; i < 4; i++) {
                    fma2(acc2[0][i], wp.x, fd[i + kx]);
                    fma2(acc2[1][i], wp.y, fd[i + kx]);
                }
            }
        }
    }

    const int yout = y0 + rowo;
#pragma unroll
    for (int jp = 0; jp < 2; jp++) {
        float vlo[4], vhi[4];
#pragma unroll
        for (int i = 0; i < 4; i++) unpack2(acc2[jp][i], vlo[i], vhi[i]);
        int oA = o0 + 2 * jp;
        int oB = oA + 1;
        if (oA < 27) {
            float bo = b_off[oA];
            float* op = &g_om[((b * 27 + oA) * HH + yout) * WW + xloc];
            *(float4*)op = make_float4(vlo[0] + bo, vlo[1] + bo, vlo[2] + bo, vlo[3] + bo);
        }
        if (oB < 27) {
            float bo = b_off[oB];
            float* op = &g_om[((b * 27 + oB) * HH + yout) * WW + xloc];
            *(float4*)op = make_float4(vhi[0] + bo, vhi[1] + bo, vhi[2] + bo, vhi[3] + bo);
        }
    }
}

// ---------------------------------------------------------------------------
// Kernel 2: fused bilinear sampling + deform GEMM + bias + ReLU.
// One CTA per (b, 2 rows): 64 o x 256 px, K = 576. 512 threads.
// Thread tile 8o x 4px with o-paired f32x2 accumulators.
// Double-buffered 32-channel sample tiles, fill pipelined ahead of GEMM.
// smem: w_s[576][64] (147KB) + 2 x vals[32][256] (64KB) = 211KB.
// ---------------------------------------------------------------------------
#define K2_W      (576 * 64)
#define K2_VBUF   (32 * 256)
#define K2_FLOATS (K2_W + 2 * K2_VBUF)
#define K2_SMEM_BYTES (K2_FLOATS * 4)

struct FillCtx {
    const float* xb;
    int b, y0, tid;
};

__device__ __forceinline__ void k2_fill(const FillCtx& fc, int tap, int cc,
                                        float* __restrict__ buf)
{
    const int px   = fc.tid & 255;
    const int cb   = (fc.tid >> 8) * 16;
    const int yrow = fc.y0 + (px >> 7);
    const int gx   = px & 127;
    const int base = ((fc.b * 27 + tap) * HH + yrow) * WW + gx;

    float offx = g_om[base];
    float offy = g_om[base + 9 * HWSZ];
    float mz   = g_om[base + 18 * HWSZ];
    float m    = 1.f / (1.f + __expf(-mz));

    float ys = (float)(yrow + tap / 3 - 1) + offy;
    float xs = (float)(gx + tap % 3 - 1) + offx;
    float y0f = floorf(ys), x0f = floorf(xs);
    float wy1 = ys - y0f,   wx1 = xs - x0f;
    int iy0 = (int)y0f, ix0 = (int)x0f;

    float cw[4];
    int   ci[4];
#pragma unroll
    for (int corner = 0; corner < 4; corner++) {
        int oy = corner >> 1, ox = corner & 1;
        int yy = iy0 + oy, xx = ix0 + ox;
        bool valid = (yy >= 0) && (yy < HH) && (xx >= 0) && (xx < WW);
        float wy = oy ? wy1 : (1.f - wy1);
        float wx = ox ? wx1 : (1.f - wx1);
        cw[corner] = valid ? (wy * wx * m) : 0.f;
        ci[corner] = min(max(yy, 0), HH - 1) * WW + min(max(xx, 0), WW - 1);
    }

    const float* xc0 = fc.xb + (size_t)(cc + cb) * HWSZ;
    float* bp = buf + cb * 256 + px;
#pragma unroll
    for (int r = 0; r < 16; r++) {
        const float* xc = xc0 + r * HWSZ;
        float v = cw[0] * xc[ci[0]] + cw[1] * xc[ci[1]]
                + cw[2] * xc[ci[2]] + cw[3] * xc[ci[3]];
        bp[r * 256] = v;
    }
}

__global__ __launch_bounds__(512, 1)
void deform_gemm_kernel(const float* __restrict__ x,
                        const float* __restrict__ w_def,
                        const float* __restrict__ b_def,
                        float* __restrict__ out)
{
    extern __shared__ float smem[];
    float* w_s   = smem;                 // [k=576][o=64]
    float* vbuf0 = smem + K2_W;
    float* vbuf1 = smem + K2_W + K2_VBUF;

    const int y0  = blockIdx.x * 2;
    const int b   = blockIdx.y;
    const int tid = threadIdx.x;

    // load w_def: w_s[k*64 + o], k = c*9 + r
    for (int idx = tid; idx < K2_W; idx += 512) {
        int o = idx & 63;
        int k = idx >> 6;
        int c = k / 9;
        int r = k - c * 9;
        w_s[idx] = w_def[(o * CC + c) * 9 + r];
    }

    const int pxa = (tid & 63) * 4;     // linear px 0..252
    const int o0  = (tid >> 6) * 8;     // warp-uniform

    FillCtx fc;
    fc.xb = x + (size_t)b * CC * HWSZ;
    fc.b = b; fc.y0 = y0; fc.tid = tid;

    u64 acc2[4][4];                     // 4 o-pairs x 4 px
#pragma unroll
    for (int j = 0; j < 4; j++)
#pragma unroll
        for (int i = 0; i < 4; i++) acc2[j][i] = 0ULL;

    float* bufs[2] = {vbuf0, vbuf1};

    // prologue: fill phase 0
    k2_fill(fc, 0, 0, vbuf0);
    __syncthreads();

    int tap_f = 1, cc_f = 0;            // fill cursor (next phase to fill)
    int tap_g = 0, cc_g = 0;            // gemm cursor

    for (int p = 0; p < 18; p++) {
        // pipeline: issue next fill into the other buffer
        if (p < 17) {
            k2_fill(fc, tap_f, cc_f, bufs[(p + 1) & 1]);
            if (++tap_f == 9) { tap_f = 0; cc_f = 32; }
        }
        // GEMM over current 32-channel chunk
        const float* vb = bufs[p & 1];
#pragma unroll 8
        for (int cl = 0; cl < 32; cl++) {
            const int k = (cc_g + cl) * 9 + tap_g;
            const float* wp = &w_s[k * 64 + o0];
            const ulonglong2 w01 = *(const ulonglong2*)wp;
            const ulonglong2 w23 = *(const ulonglong2*)(wp + 4);
            const float4 v = *(const float4*)&vb[cl * 256 + pxa];
            u64 vd[4] = {dup2(v.x), dup2(v.y), dup2(v.z), dup2(v.w)};
            u64 wv[4] = {w01.x, w01.y, w23.x, w23.y};
#pragma unroll
            for (int j = 0; j < 4; j++)
#pragma unroll
                for (int i = 0; i < 4; i++)
                    fma2(acc2[j][i], wv[j], vd[i]);
        }
        if (++tap_g == 9) { tap_g = 0; cc_g = 32; }
        __syncthreads();
    }

    // epilogue: unpack o-pairs, bias + relu, float4 stores
    const int yrow = y0 + (pxa >> 7);
    const int xcol = pxa & 127;
#pragma unroll
    for (int jp = 0; jp < 4; jp++) {
        float vlo[4], vhi[4];
#pragma unroll
        for (int i = 0; i < 4; i++) unpack2(acc2[jp][i], vlo[i], vhi[i]);
        int oA = o0 + 2 * jp;
        int oB = oA + 1;
        float bA = b_def[oA], bB = b_def[oB];
        float* opA = out + ((size_t)(b * OO + oA) * HH + yrow) * WW + xcol;
        float* opB = out + ((size_t)(b * OO + oB) * HH + yrow) * WW + xcol;
        *(float4*)opA = make_float4(fmaxf(vlo[0] + bA, 0.f), fmaxf(vlo[1] + bA, 0.f),
                                    fmaxf(vlo[2] + bA, 0.f), fmaxf(vlo[3] + bA, 0.f));
        *(float4*)opB = make_float4(fmaxf(vhi[0] + bB, 0.f), fmaxf(vhi[1] + bB, 0.f),
                                    fmaxf(vhi[2] + bB, 0.f), fmaxf(vhi[3] + bB, 0.f));
    }
}

// ---------------------------------------------------------------------------
extern "C" void kernel_launch(void* const* d_in, const int* in_sizes, int n_in,
                              void* d_out, int out_size)
{
    const float* x     = (const float*)d_in[0];
    const float* feat  = (const float*)d_in[1];
    const float* w_off = (const float*)d_in[2];
    const float* b_off = (const float*)d_in[3];
    const float* w_def = (const float*)d_in[4];
    const float* b_def = (const float*)d_in[5];
    float* out = (float*)d_out;

    cudaFuncSetAttribute(offset_conv_kernel,
                         cudaFuncAttributeMaxDynamicSharedMemorySize, K1_SMEM_BYTES);
    cudaFuncSetAttribute(deform_gemm_kernel,
                         cudaFuncAttributeMaxDynamicSharedMemorySize, K2_SMEM_BYTES);

    dim3 grid(HH / 2, BB);
    offset_conv_kernel<<<grid, 512, K1_SMEM_BYTES>>>(feat, w_off, b_off);
    deform_gemm_kernel<<<grid, 512, K2_SMEM_BYTES>>>(x, w_def, b_def, out);
}